// round 9
// baseline (speedup 1.0000x reference)
#include <cuda_runtime.h>
#include <cuda_fp16.h>
#include <math.h>
#include <stdint.h>

#define NE    32
#define KTOP  4
#define HDIM  1024
#define IDIM  512
#define TTOK  4096
#define CAP   1024

// ---------------- device scratch ----------------
__device__ int   g_count[NE];
__device__ int   g_tok[NE * CAP];
__device__ int   g_e4[TTOK * KTOP];
__device__ int   g_s4[TTOK * KTOP];
__device__ float g_w4[TTOK * KTOP];
__device__ float g_act[(size_t)NE * CAP * IDIM];
__device__ float g_shact[(size_t)TTOK * IDIM];
__device__ float g_dbuf[(size_t)NE * CAP * HDIM];

// ---------------- helpers ----------------
__device__ __forceinline__ uint32_t pack2(float lo, float hi) {
    __half2 h = __floats2half2_rn(lo, hi);
    return *(uint32_t*)&h;
}
__device__ __forceinline__ void mma16(float* c, const uint32_t* a,
                                      uint32_t b0, uint32_t b1) {
    asm volatile(
        "mma.sync.aligned.m16n8k16.row.col.f32.f16.f16.f32 "
        "{%0,%1,%2,%3}, {%4,%5,%6,%7}, {%8,%9}, {%0,%1,%2,%3};"
        : "+f"(c[0]), "+f"(c[1]), "+f"(c[2]), "+f"(c[3])
        : "r"(a[0]), "r"(a[1]), "r"(a[2]), "r"(a[3]), "r"(b0), "r"(b1));
}

// ---------------- router ----------------
__global__ void zero_counts_kernel() {
    if (threadIdx.x < NE) g_count[threadIdx.x] = 0;
}

__global__ void router_kernel(const float* __restrict__ x,
                              const float* __restrict__ gw) {
    const int t = blockIdx.x;
    __shared__ float xs[HDIM];
    __shared__ float logits[NE];
    const float* xr = x + (size_t)t * HDIM;
    for (int i = threadIdx.x; i < HDIM; i += 128) xs[i] = xr[i];
    __syncthreads();

    const int warp = threadIdx.x >> 5, lane = threadIdx.x & 31;
    for (int i = 0; i < 8; i++) {
        const int e = warp * 8 + i;
        const float* w = gw + (size_t)e * HDIM;
        float s = 0.f;
        #pragma unroll 8
        for (int j = lane; j < HDIM; j += 32) s += xs[j] * w[j];
        #pragma unroll
        for (int o = 16; o > 0; o >>= 1) s += __shfl_down_sync(0xffffffffu, s, o);
        if (lane == 0) logits[e] = s;
    }
    __syncthreads();

    if (threadIdx.x == 0) {
        float mx = logits[0];
        #pragma unroll
        for (int e = 1; e < NE; e++) mx = fmaxf(mx, logits[e]);
        float p[NE];
        #pragma unroll
        for (int e = 0; e < NE; e++) p[e] = expf(logits[e] - mx);
        int idx[KTOP]; float pv[KTOP]; float psum = 0.f;
        bool used[NE];
        #pragma unroll
        for (int e = 0; e < NE; e++) used[e] = false;
        for (int k = 0; k < KTOP; k++) {
            float best = -1.f; int bi = 0;
            for (int e = 0; e < NE; e++)
                if (!used[e] && p[e] > best) { best = p[e]; bi = e; }
            used[bi] = true; idx[k] = bi; pv[k] = best; psum += best;
        }
        const float inv = 1.f / psum;
        for (int k = 0; k < KTOP; k++) {
            const int e = idx[k];
            const int pos = atomicAdd(&g_count[e], 1);
            if (pos < CAP) g_tok[e * CAP + pos] = t;
            g_e4[t * KTOP + k] = e;
            g_s4[t * KTOP + k] = pos;
            g_w4[t * KTOP + k] = pv[k] * inv;
        }
    }
}

// ---------------- GEMM layout (fp16 half2 along K) ----------------
// A smem: 128 rows x 16 kp (K=32), row stride 20 -> frag LDS conflict-free
// B smem: 16 kp x 128 n, row stride 136 -> frag LDS conflict-free
#define ASZ 2560   // 128*20 words
#define BSZ 2176   // 16*136 words

// Shared staging index vocabulary (256 threads):
//   A LDG: i in 0..3 : row = i*32 + (tid>>3), float col (tid&7)*4  (4-line LDG)
//   A STS: 2x uint2 per i at word (row*20 + (tid&7)*2)
//   B LDG: kp2 = tid>>5 (==wid), bq = tid&31; kp rows {kp2, kp2+8};
//          per kp: k rows 2kp,2kp+1 at float col bq*4 (coalesced 512B)
//   B STS: uint4 at word (kp*136 + bq*4) (conflict-free per 8-lane phase)

// ---------------- gate-up (fp16 mma.sync, fused silu) ----------------
// 256 thr, 8 warps (4M x 2N). block: M=128, N=64 gate + 64 up.
// warp: m32 x (n32 gate + n32 up). K chunks of 32 (2 kf of K=16). 64 accums.
template <bool EXPERT>
__global__ void __launch_bounds__(256, 2)
gu_mma(const float* __restrict__ X, const float* __restrict__ Wgu) {
    const int e = EXPERT ? blockIdx.z : 0;
    const int n_e = EXPERT ? min(g_count[e], CAP) : TTOK;
    const int m0 = blockIdx.y * 128;
    if (m0 >= n_e) return;
    const int n0 = blockIdx.x * 64;

    __shared__ uint32_t As_[2 * ASZ];
    __shared__ uint32_t Bs_[2 * BSZ];

    const int tid = threadIdx.x;
    const int wid = tid >> 5, lane = tid & 31;
    const int g = lane >> 2, tig = lane & 3;
    const int wm = wid & 3, wn = wid >> 2;

    const float* W = EXPERT ? Wgu + (size_t)e * HDIM * (2 * IDIM) : Wgu;
    float* actb = EXPERT ? g_act + (size_t)e * CAP * IDIM : g_shact;

    // A gather pointers (4 rows per thread)
    const int r8 = tid >> 3, aq = tid & 7;
    const float* arow[4];
    #pragma unroll
    for (int i = 0; i < 4; i++) {
        const int r = m0 + i * 32 + r8;
        const float* p = nullptr;
        if (r < n_e) p = X + (size_t)(EXPERT ? g_tok[e * CAP + r] : r) * HDIM;
        arow[i] = p;
    }
    const int kp2 = wid, bq = lane;
    const int bcol = (bq < 16) ? (n0 + bq * 4) : (IDIM + n0 + (bq - 16) * 4);

    float cg[2][4][4], cu[2][4][4];
    #pragma unroll
    for (int a = 0; a < 2; a++)
        #pragma unroll
        for (int b = 0; b < 4; b++)
            #pragma unroll
            for (int d = 0; d < 4; d++) { cg[a][b][d] = 0.f; cu[a][b][d] = 0.f; }

    const int abase = (wm * 32 + g) * 20 + tig;
    const int bbase = tig * 136 + wn * 32 + g;

    float4 ra[4], rb[4];
    #define GU_LDG(k0) do { \
        _Pragma("unroll") \
        for (int i = 0; i < 4; i++) \
            ra[i] = arow[i] ? *(const float4*)(arow[i] + (k0) + aq * 4) \
                            : make_float4(0.f, 0.f, 0.f, 0.f); \
        _Pragma("unroll") \
        for (int j = 0; j < 2; j++) { \
            const int kk = (k0) + 2 * (kp2 + j * 8); \
            rb[j * 2 + 0] = *(const float4*)(W + (size_t)kk * (2 * IDIM) + bcol); \
            rb[j * 2 + 1] = *(const float4*)(W + (size_t)(kk + 1) * (2 * IDIM) + bcol); \
        } \
    } while (0)
    #define GU_STS(bufi) do { \
        _Pragma("unroll") \
        for (int i = 0; i < 4; i++) { \
            uint2 u; \
            u.x = pack2(ra[i].x, ra[i].y); \
            u.y = pack2(ra[i].z, ra[i].w); \
            *(uint2*)&As_[(bufi) * ASZ + (i * 32 + r8) * 20 + aq * 2] = u; \
        } \
        _Pragma("unroll") \
        for (int j = 0; j < 2; j++) { \
            const int kp = kp2 + j * 8; \
            uint4 u; \
            u.x = pack2(rb[j * 2].x, rb[j * 2 + 1].x); \
            u.y = pack2(rb[j * 2].y, rb[j * 2 + 1].y); \
            u.z = pack2(rb[j * 2].z, rb[j * 2 + 1].z); \
            u.w = pack2(rb[j * 2].w, rb[j * 2 + 1].w); \
            *(uint4*)&Bs_[(bufi) * BSZ + kp * 136 + bq * 4] = u; \
        } \
    } while (0)
    #define GU_COMP(kf) do { \
        uint32_t a[2][4]; \
        _Pragma("unroll") \
        for (int mf = 0; mf < 2; mf++) { \
            const int o = abase + mf * 320 + (kf) * 8; \
            a[mf][0] = Ab[o];     a[mf][1] = Ab[o + 160]; \
            a[mf][2] = Ab[o + 4]; a[mf][3] = Ab[o + 164]; \
        } \
        _Pragma("unroll") \
        for (int nf = 0; nf < 4; nf++) { \
            const int ob = bbase + (kf) * 1088 + nf * 8; \
            const uint32_t bg0 = Bb[ob],      bg1 = Bb[ob + 544]; \
            const uint32_t bu0 = Bb[ob + 64], bu1 = Bb[ob + 608]; \
            _Pragma("unroll") \
            for (int mf = 0; mf < 2; mf++) { \
                mma16(cg[mf][nf], a[mf], bg0, bg1); \
                mma16(cu[mf][nf], a[mf], bu0, bu1); \
            } \
        } \
    } while (0)

    GU_LDG(0); GU_STS(0);
    __syncthreads();

    const int NC = HDIM / 32;
    for (int c = 0; c < NC; c++) {
        const int buf = c & 1;
        const uint32_t* Ab = As_ + buf * ASZ;
        const uint32_t* Bb = Bs_ + buf * BSZ;
        const bool more = (c + 1 < NC);
        if (more) GU_LDG((c + 1) * 32);
        GU_COMP(0);
        if (more) GU_STS(buf ^ 1);
        GU_COMP(1);
        __syncthreads();
    }
    #undef GU_LDG
    #undef GU_STS
    #undef GU_COMP

    // epilogue: silu(gate)*up
    #pragma unroll
    for (int mf = 0; mf < 2; mf++) {
        #pragma unroll
        for (int nf = 0; nf < 4; nf++) {
            const int row0 = m0 + wm * 32 + mf * 16 + g;
            const int col  = n0 + wn * 32 + nf * 8 + tig * 2;
            if (row0 < n_e) {
                float gv, uv; float2 o;
                gv = cg[mf][nf][0]; uv = cu[mf][nf][0]; o.x = gv / (1.f + __expf(-gv)) * uv;
                gv = cg[mf][nf][1]; uv = cu[mf][nf][1]; o.y = gv / (1.f + __expf(-gv)) * uv;
                *(float2*)(actb + (size_t)row0 * IDIM + col) = o;
            }
            if (row0 + 8 < n_e) {
                float gv, uv; float2 o;
                gv = cg[mf][nf][2]; uv = cu[mf][nf][2]; o.x = gv / (1.f + __expf(-gv)) * uv;
                gv = cg[mf][nf][3]; uv = cu[mf][nf][3]; o.y = gv / (1.f + __expf(-gv)) * uv;
                *(float2*)(actb + (size_t)(row0 + 8) * IDIM + col) = o;
            }
        }
    }
}

// ---------------- down (fp16 mma.sync) ----------------
// 256 thr, 8 warps (4M x 2N). block M=128 x N=128; warp m32 x n64. 64 accums.
template <bool EXPERT>
__global__ void __launch_bounds__(256, 2)
dn_mma(const float* __restrict__ Wd, float* __restrict__ out) {
    const int e = EXPERT ? blockIdx.z : 0;
    const int n_e = EXPERT ? min(g_count[e], CAP) : TTOK;
    const int m0 = blockIdx.y * 128;
    if (m0 >= n_e) return;
    const int n0 = blockIdx.x * 128;

    __shared__ uint32_t As_[2 * ASZ];
    __shared__ uint32_t Bs_[2 * BSZ];

    const int tid = threadIdx.x;
    const int wid = tid >> 5, lane = tid & 31;
    const int g = lane >> 2, tig = lane & 3;
    const int wm = wid & 3, wn = wid >> 2;

    const float* actb = EXPERT ? g_act + (size_t)e * CAP * IDIM : g_shact;
    const float* W = EXPERT ? Wd + (size_t)e * IDIM * HDIM : Wd;

    const int r8 = tid >> 3, aq = tid & 7;
    const float* arow[4];
    #pragma unroll
    for (int i = 0; i < 4; i++)
        arow[i] = actb + (size_t)(m0 + i * 32 + r8) * IDIM;
    const int kp2 = wid, bq = lane;
    const int bcol = n0 + bq * 4;

    float cc[2][8][4];
    #pragma unroll
    for (int a = 0; a < 2; a++)
        #pragma unroll
        for (int b = 0; b < 8; b++)
            #pragma unroll
            for (int d = 0; d < 4; d++) cc[a][b][d] = 0.f;

    const int abase = (wm * 32 + g) * 20 + tig;
    const int bbase = tig * 136 + wn * 64 + g;

    float4 ra[4], rb[4];
    #define DN_LDG(k0) do { \
        _Pragma("unroll") \
        for (int i = 0; i < 4; i++) \
            ra[i] = *(const float4*)(arow[i] + (k0) + aq * 4); \
        _Pragma("unroll") \
        for (int j = 0; j < 2; j++) { \
            const int kk = (k0) + 2 * (kp2 + j * 8); \
            rb[j * 2 + 0] = *(const float4*)(W + (size_t)kk * HDIM + bcol); \
            rb[j * 2 + 1] = *(const float4*)(W + (size_t)(kk + 1) * HDIM + bcol); \
        } \
    } while (0)
    #define DN_STS(bufi) do { \
        _Pragma("unroll") \
        for (int i = 0; i < 4; i++) { \
            uint2 u; \
            u.x = pack2(ra[i].x, ra[i].y); \
            u.y = pack2(ra[i].z, ra[i].w); \
            *(uint2*)&As_[(bufi) * ASZ + (i * 32 + r8) * 20 + aq * 2] = u; \
        } \
        _Pragma("unroll") \
        for (int j = 0; j < 2; j++) { \
            const int kp = kp2 + j * 8; \
            uint4 u; \
            u.x = pack2(rb[j * 2].x, rb[j * 2 + 1].x); \
            u.y = pack2(rb[j * 2].y, rb[j * 2 + 1].y); \
            u.z = pack2(rb[j * 2].z, rb[j * 2 + 1].z); \
            u.w = pack2(rb[j * 2].w, rb[j * 2 + 1].w); \
            *(uint4*)&Bs_[(bufi) * BSZ + kp * 136 + bq * 4] = u; \
        } \
    } while (0)
    #define DN_COMP(kf) do { \
        uint32_t a[2][4]; \
        _Pragma("unroll") \
        for (int mf = 0; mf < 2; mf++) { \
            const int o = abase + mf * 320 + (kf) * 8; \
            a[mf][0] = Ab[o];     a[mf][1] = Ab[o + 160]; \
            a[mf][2] = Ab[o + 4]; a[mf][3] = Ab[o + 164]; \
        } \
        _Pragma("unroll") \
        for (int nf = 0; nf < 8; nf++) { \
            const int ob = bbase + (kf) * 1088 + nf * 8; \
            const uint32_t b0 = Bb[ob], b1 = Bb[ob + 544]; \
            _Pragma("unroll") \
            for (int mf = 0; mf < 2; mf++) \
                mma16(cc[mf][nf], a[mf], b0, b1); \
        } \
    } while (0)

    DN_LDG(0); DN_STS(0);
    __syncthreads();

    const int NC = IDIM / 32;
    for (int c = 0; c < NC; c++) {
        const int buf = c & 1;
        const uint32_t* Ab = As_ + buf * ASZ;
        const uint32_t* Bb = Bs_ + buf * BSZ;
        const bool more = (c + 1 < NC);
        if (more) DN_LDG((c + 1) * 32);
        DN_COMP(0);
        if (more) DN_STS(buf ^ 1);
        DN_COMP(1);
        __syncthreads();
    }
    #undef DN_LDG
    #undef DN_STS
    #undef DN_COMP

    #pragma unroll
    for (int mf = 0; mf < 2; mf++) {
        #pragma unroll
        for (int nf = 0; nf < 8; nf++) {
            const int row0 = m0 + wm * 32 + mf * 16 + g;
            const int col  = n0 + wn * 64 + nf * 8 + tig * 2;
            if (row0 < n_e) {
                float* dst = EXPERT ? (g_dbuf + ((size_t)e * CAP + row0) * HDIM + col)
                                    : (out + (size_t)row0 * HDIM + col);
                *(float2*)dst = make_float2(cc[mf][nf][0], cc[mf][nf][1]);
            }
            if (row0 + 8 < n_e) {
                float* dst = EXPERT ? (g_dbuf + ((size_t)e * CAP + row0 + 8) * HDIM + col)
                                    : (out + (size_t)(row0 + 8) * HDIM + col);
                *(float2*)dst = make_float2(cc[mf][nf][2], cc[mf][nf][3]);
            }
        }
    }
}

// ---------------- combine ----------------
__global__ void __launch_bounds__(256)
combine_kernel(float* __restrict__ out) {
    const int t = blockIdx.x;
    const int i = threadIdx.x;
    float4 acc = ((const float4*)out)[(size_t)t * 256 + i];
    #pragma unroll
    for (int k = 0; k < KTOP; k++) {
        const int e = g_e4[t * KTOP + k];
        const int s = g_s4[t * KTOP + k];
        const float w = g_w4[t * KTOP + k];
        if (s < CAP) {
            const float4 v = ((const float4*)g_dbuf)[((size_t)e * CAP + s) * (HDIM / 4) + i];
            acc.x += w * v.x; acc.y += w * v.y; acc.z += w * v.z; acc.w += w * v.w;
        }
    }
    ((float4*)out)[(size_t)t * 256 + i] = acc;
}

extern "C" void kernel_launch(void* const* d_in, const int* in_sizes, int n_in,
                              void* d_out, int out_size) {
    const float* x   = (const float*)d_in[0];
    const float* gw  = (const float*)d_in[1];
    const float* wgu = (const float*)d_in[2];
    const float* wd  = (const float*)d_in[3];
    const float* sgu = (const float*)d_in[4];
    const float* sd  = (const float*)d_in[5];
    float* out = (float*)d_out;
    (void)in_sizes; (void)n_in; (void)out_size;

    zero_counts_kernel<<<1, 32>>>();
    router_kernel<<<TTOK, 128>>>(x, gw);

    gu_mma<true ><<<dim3(IDIM / 64, CAP / 128, NE), 256>>>(x, wgu);
    gu_mma<false><<<dim3(IDIM / 64, TTOK / 128, 1), 256>>>(x, sgu);

    dn_mma<true ><<<dim3(HDIM / 128, CAP / 128, NE), 256>>>(wd, out);
    dn_mma<false><<<dim3(HDIM / 128, TTOK / 128, 1), 256>>>(sd, out);

    combine_kernel<<<TTOK, 256>>>(out);
}

// round 12
// speedup vs baseline: 1.1368x; 1.1368x over previous
#include <cuda_runtime.h>
#include <cuda_fp16.h>
#include <math.h>
#include <stdint.h>

#define NE    32
#define KTOP  4
#define HDIM  1024
#define IDIM  512
#define TTOK  4096
#define CAP   1024

// ---------------- device scratch ----------------
__device__ int   g_count[NE];
__device__ int   g_tok[NE * CAP];
__device__ int   g_e4[TTOK * KTOP];
__device__ int   g_s4[TTOK * KTOP];
__device__ float g_w4[TTOK * KTOP];
__device__ float g_act[(size_t)NE * CAP * IDIM];
__device__ float g_shact[(size_t)TTOK * IDIM];
__device__ float g_dbuf[(size_t)NE * CAP * HDIM];

// ---------------- helpers ----------------
__device__ __forceinline__ uint32_t pack2(float lo, float hi) {
    __half2 h = __floats2half2_rn(lo, hi);
    return *(uint32_t*)&h;
}
__device__ __forceinline__ void mma16(float* c, const uint32_t* a,
                                      uint32_t b0, uint32_t b1) {
    asm volatile(
        "mma.sync.aligned.m16n8k16.row.col.f32.f16.f16.f32 "
        "{%0,%1,%2,%3}, {%4,%5,%6,%7}, {%8,%9}, {%0,%1,%2,%3};"
        : "+f"(c[0]), "+f"(c[1]), "+f"(c[2]), "+f"(c[3])
        : "r"(a[0]), "r"(a[1]), "r"(a[2]), "r"(a[3]), "r"(b0), "r"(b1));
}
__device__ __forceinline__ void ldsm4(uint32_t* r, uint32_t saddr) {
    asm volatile("ldmatrix.sync.aligned.m8n8.x4.shared.b16 {%0,%1,%2,%3}, [%4];"
        : "=r"(r[0]), "=r"(r[1]), "=r"(r[2]), "=r"(r[3]) : "r"(saddr));
}
__device__ __forceinline__ uint32_t smem_u32(const void* p) {
    return (uint32_t)__cvta_generic_to_shared(p);
}

// ---------------- router ----------------
__global__ void zero_counts_kernel() {
    if (threadIdx.x < NE) g_count[threadIdx.x] = 0;
}

__global__ void router_kernel(const float* __restrict__ x,
                              const float* __restrict__ gw) {
    const int t = blockIdx.x;
    __shared__ float xs[HDIM];
    __shared__ float logits[NE];
    const float* xr = x + (size_t)t * HDIM;
    for (int i = threadIdx.x; i < HDIM; i += 128) xs[i] = xr[i];
    __syncthreads();

    const int warp = threadIdx.x >> 5, lane = threadIdx.x & 31;
    for (int i = 0; i < 8; i++) {
        const int e = warp * 8 + i;
        const float* w = gw + (size_t)e * HDIM;
        float s = 0.f;
        #pragma unroll 8
        for (int j = lane; j < HDIM; j += 32) s += xs[j] * w[j];
        #pragma unroll
        for (int o = 16; o > 0; o >>= 1) s += __shfl_down_sync(0xffffffffu, s, o);
        if (lane == 0) logits[e] = s;
    }
    __syncthreads();

    if (threadIdx.x == 0) {
        float mx = logits[0];
        #pragma unroll
        for (int e = 1; e < NE; e++) mx = fmaxf(mx, logits[e]);
        float p[NE];
        #pragma unroll
        for (int e = 0; e < NE; e++) p[e] = expf(logits[e] - mx);
        int idx[KTOP]; float pv[KTOP]; float psum = 0.f;
        bool used[NE];
        #pragma unroll
        for (int e = 0; e < NE; e++) used[e] = false;
        for (int k = 0; k < KTOP; k++) {
            float best = -1.f; int bi = 0;
            for (int e = 0; e < NE; e++)
                if (!used[e] && p[e] > best) { best = p[e]; bi = e; }
            used[bi] = true; idx[k] = bi; pv[k] = best; psum += best;
        }
        const float inv = 1.f / psum;
        for (int k = 0; k < KTOP; k++) {
            const int e = idx[k];
            const int pos = atomicAdd(&g_count[e], 1);
            if (pos < CAP) g_tok[e * CAP + pos] = t;
            g_e4[t * KTOP + k] = e;
            g_s4[t * KTOP + k] = pos;
            g_w4[t * KTOP + k] = pv[k] * inv;
        }
    }
}

// ---------------- GEMM layout (fp16 half2 along K) ----------------
// A smem: 128 rows x 16 kp (K=32 halves), row stride 20 words.
//   LDSM conflict-free: 16B-chunk index (5r + c) mod 8 is a permutation.
// B smem: 16 kp x 128 n, row stride 136 words (scalar frag LDS conflict-free).
#define ASZ 2560   // words
#define BSZ 2176   // words

// Merged grid decode: bids [0,2048) = expert (z = bid>>6, my = (bid>>3)&7,
// nx = bid&7); bids [2048,2304) = shared (my = r>>3 in 0..31, nx = r&7).

// ---------------- gate-up (fp16 mma.sync, fused silu, merged) ----------------
// 128 thr, 4 warps (2M x 2N). block M=128, N=64 gate + 64 up. warp m64.
__global__ void __launch_bounds__(128)
gu_mma(const float* __restrict__ X, const float* __restrict__ Wge,
       const float* __restrict__ Wgs) {
    const int bid = blockIdx.x;
    const bool EXP = bid < 2048;
    int ez, my, nx;
    if (EXP) { ez = bid >> 6; my = (bid >> 3) & 7; nx = bid & 7; }
    else     { const int r = bid - 2048; ez = 0; my = r >> 3; nx = r & 7; }
    const int n_e = EXP ? min(g_count[ez], CAP) : TTOK;
    const int m0 = my * 128;
    if (m0 >= n_e) return;
    const int n0 = nx * 64;

    __shared__ uint32_t As_[2 * ASZ];
    __shared__ uint32_t Bs_[2 * BSZ];

    const int tid = threadIdx.x;
    const int wid = tid >> 5, lane = tid & 31;
    const int g = lane >> 2, tig = lane & 3;
    const int wm = wid & 1, wn = wid >> 1;

    const float* W = EXP ? Wge + (size_t)ez * HDIM * (2 * IDIM) : Wgs;
    float* actb = EXP ? g_act + (size_t)ez * CAP * IDIM : g_shact;

    // A staging: one row per thread
    const float* arow = nullptr;
    {
        const int r = m0 + tid;
        if (r < n_e) arow = X + (size_t)(EXP ? g_tok[ez * CAP + r] : r) * HDIM;
    }
    const int bk = wid, bq = lane;
    const int bcol = (bq < 16) ? (n0 + bq * 4) : (IDIM + n0 + (bq - 16) * 4);

    float cg[4][4][4], cu[4][4][4];
    #pragma unroll
    for (int a = 0; a < 4; a++)
        #pragma unroll
        for (int b = 0; b < 4; b++)
            #pragma unroll
            for (int d = 0; d < 4; d++) { cg[a][b][d] = 0.f; cu[a][b][d] = 0.f; }

    // ldmatrix per-thread address (bytes): tile row/col by lane
    const uint32_t As_bytes = smem_u32(As_);
    const int lrow = (lane & 7) + ((lane >> 3) & 1) * 8;
    const int lcol = (lane >> 4) * 4;
    const uint32_t a_off = (uint32_t)(((wm * 64 + lrow) * 20 + lcol) * 4);
    const int bbase = tig * 136 + wn * 32 + g;

    float4 ra[4], rb[4];
    #define GU_LDGA(k0, h) do { \
        _Pragma("unroll") \
        for (int j = 0; j < 4; j++) \
            ra[j] = arow ? *(const float4*)(arow + (k0) + (h) * 16 + j * 4) \
                         : make_float4(0.f, 0.f, 0.f, 0.f); \
    } while (0)
    #define GU_LDGB(k0, h) do { \
        _Pragma("unroll") \
        for (int q2 = 0; q2 < 2; q2++) { \
            const int kk = (k0) + 2 * (bk + ((h) * 2 + q2) * 4); \
            rb[q2 * 2 + 0] = *(const float4*)(W + (size_t)kk * (2 * IDIM) + bcol); \
            rb[q2 * 2 + 1] = *(const float4*)(W + (size_t)(kk + 1) * (2 * IDIM) + bcol); \
        } \
    } while (0)
    #define GU_STS(bufi, h) do { \
        _Pragma("unroll") \
        for (int q2 = 0; q2 < 2; q2++) { \
            uint4 u; \
            u.x = pack2(ra[q2 * 2].x, ra[q2 * 2].y); \
            u.y = pack2(ra[q2 * 2].z, ra[q2 * 2].w); \
            u.z = pack2(ra[q2 * 2 + 1].x, ra[q2 * 2 + 1].y); \
            u.w = pack2(ra[q2 * 2 + 1].z, ra[q2 * 2 + 1].w); \
            *(uint4*)&As_[(bufi) * ASZ + tid * 20 + ((h) * 2 + q2) * 4] = u; \
        } \
        _Pragma("unroll") \
        for (int q2 = 0; q2 < 2; q2++) { \
            const int kp = bk + ((h) * 2 + q2) * 4; \
            uint4 u; \
            u.x = pack2(rb[q2 * 2].x, rb[q2 * 2 + 1].x); \
            u.y = pack2(rb[q2 * 2].y, rb[q2 * 2 + 1].y); \
            u.z = pack2(rb[q2 * 2].z, rb[q2 * 2 + 1].z); \
            u.w = pack2(rb[q2 * 2].w, rb[q2 * 2 + 1].w); \
            *(uint4*)&Bs_[(bufi) * BSZ + kp * 136 + bq * 4] = u; \
        } \
    } while (0)
    #define GU_COMP(kf) do { \
        uint32_t a[4][4]; \
        _Pragma("unroll") \
        for (int mf = 0; mf < 4; mf++) \
            ldsm4(a[mf], Aaddr + mf * 1280 + (kf) * 32); \
        _Pragma("unroll") \
        for (int nf = 0; nf < 4; nf++) { \
            const int ob = bbase + (kf) * 1088 + nf * 8; \
            const uint32_t bg0 = Bb[ob],      bg1 = Bb[ob + 544]; \
            const uint32_t bu0 = Bb[ob + 64], bu1 = Bb[ob + 608]; \
            _Pragma("unroll") \
            for (int mf = 0; mf < 4; mf++) { \
                mma16(cg[mf][nf], a[mf], bg0, bg1); \
                mma16(cu[mf][nf], a[mf], bu0, bu1); \
            } \
        } \
    } while (0)

    GU_LDGA(0, 0);  GU_LDGB(0, 0);  GU_STS(0, 0);
    GU_LDGA(0, 1);  GU_LDGB(0, 1);  GU_STS(0, 1);
    __syncthreads();

    const int NC = HDIM / 32;
    for (int c = 0; c < NC; c++) {
        const int buf = c & 1;
        const uint32_t Aaddr = As_bytes + (uint32_t)buf * (ASZ * 4) + a_off;
        const uint32_t* Bb = Bs_ + buf * BSZ;
        const bool more = (c + 1 < NC);
        if (more) { GU_LDGA((c + 1) * 32, 0); GU_LDGB((c + 1) * 32, 0); }
        GU_COMP(0);
        if (more) { GU_STS(buf ^ 1, 0); GU_LDGA((c + 1) * 32, 1); GU_LDGB((c + 1) * 32, 1); }
        GU_COMP(1);
        if (more) { GU_STS(buf ^ 1, 1); }
        __syncthreads();
    }
    #undef GU_LDGA
    #undef GU_LDGB
    #undef GU_STS
    #undef GU_COMP

    // epilogue: silu(gate)*up
    #pragma unroll
    for (int mf = 0; mf < 4; mf++) {
        #pragma unroll
        for (int nf = 0; nf < 4; nf++) {
            const int row0 = m0 + wm * 64 + mf * 16 + g;
            const int col  = n0 + wn * 32 + nf * 8 + tig * 2;
            if (row0 < n_e) {
                float gv, uv; float2 o;
                gv = cg[mf][nf][0]; uv = cu[mf][nf][0]; o.x = gv / (1.f + __expf(-gv)) * uv;
                gv = cg[mf][nf][1]; uv = cu[mf][nf][1]; o.y = gv / (1.f + __expf(-gv)) * uv;
                *(float2*)(actb + (size_t)row0 * IDIM + col) = o;
            }
            if (row0 + 8 < n_e) {
                float gv, uv; float2 o;
                gv = cg[mf][nf][2]; uv = cu[mf][nf][2]; o.x = gv / (1.f + __expf(-gv)) * uv;
                gv = cg[mf][nf][3]; uv = cu[mf][nf][3]; o.y = gv / (1.f + __expf(-gv)) * uv;
                *(float2*)(actb + (size_t)(row0 + 8) * IDIM + col) = o;
            }
        }
    }
}

// ---------------- down (fp16 mma.sync, merged) ----------------
// 128 thr, 4 warps (2M x 2N). block M=128 x N=128; warp m64 x n64.
__global__ void __launch_bounds__(128)
dn_mma(const float* __restrict__ Wde, const float* __restrict__ Wds,
       float* __restrict__ out) {
    const int bid = blockIdx.x;
    const bool EXP = bid < 2048;
    int ez, my, nx;
    if (EXP) { ez = bid >> 6; my = (bid >> 3) & 7; nx = bid & 7; }
    else     { const int r = bid - 2048; ez = 0; my = r >> 3; nx = r & 7; }
    const int n_e = EXP ? min(g_count[ez], CAP) : TTOK;
    const int m0 = my * 128;
    if (m0 >= n_e) return;
    const int n0 = nx * 128;

    __shared__ uint32_t As_[2 * ASZ];
    __shared__ uint32_t Bs_[2 * BSZ];

    const int tid = threadIdx.x;
    const int wid = tid >> 5, lane = tid & 31;
    const int g = lane >> 2, tig = lane & 3;
    const int wm = wid & 1, wn = wid >> 1;

    const float* actb = EXP ? g_act + (size_t)ez * CAP * IDIM : g_shact;
    const float* W = EXP ? Wde + (size_t)ez * IDIM * HDIM : Wds;

    const float* arow = actb + (size_t)(m0 + tid) * IDIM;
    const int bk = wid, bq = lane;
    const int bcol = n0 + bq * 4;

    float cc[4][8][4];
    #pragma unroll
    for (int a = 0; a < 4; a++)
        #pragma unroll
        for (int b = 0; b < 8; b++)
            #pragma unroll
            for (int d = 0; d < 4; d++) cc[a][b][d] = 0.f;

    const uint32_t As_bytes = smem_u32(As_);
    const int lrow = (lane & 7) + ((lane >> 3) & 1) * 8;
    const int lcol = (lane >> 4) * 4;
    const uint32_t a_off = (uint32_t)(((wm * 64 + lrow) * 20 + lcol) * 4);
    const int bbase = tig * 136 + wn * 64 + g;

    float4 ra[4], rb[4];
    #define DN_LDGA(k0, h) do { \
        _Pragma("unroll") \
        for (int j = 0; j < 4; j++) \
            ra[j] = *(const float4*)(arow + (k0) + (h) * 16 + j * 4); \
    } while (0)
    #define DN_LDGB(k0, h) do { \
        _Pragma("unroll") \
        for (int q2 = 0; q2 < 2; q2++) { \
            const int kk = (k0) + 2 * (bk + ((h) * 2 + q2) * 4); \
            rb[q2 * 2 + 0] = *(const float4*)(W + (size_t)kk * HDIM + bcol); \
            rb[q2 * 2 + 1] = *(const float4*)(W + (size_t)(kk + 1) * HDIM + bcol); \
        } \
    } while (0)
    #define DN_STS(bufi, h) do { \
        _Pragma("unroll") \
        for (int q2 = 0; q2 < 2; q2++) { \
            uint4 u; \
            u.x = pack2(ra[q2 * 2].x, ra[q2 * 2].y); \
            u.y = pack2(ra[q2 * 2].z, ra[q2 * 2].w); \
            u.z = pack2(ra[q2 * 2 + 1].x, ra[q2 * 2 + 1].y); \
            u.w = pack2(ra[q2 * 2 + 1].z, ra[q2 * 2 + 1].w); \
            *(uint4*)&As_[(bufi) * ASZ + tid * 20 + ((h) * 2 + q2) * 4] = u; \
        } \
        _Pragma("unroll") \
        for (int q2 = 0; q2 < 2; q2++) { \
            const int kp = bk + ((h) * 2 + q2) * 4; \
            uint4 u; \
            u.x = pack2(rb[q2 * 2].x, rb[q2 * 2 + 1].x); \
            u.y = pack2(rb[q2 * 2].y, rb[q2 * 2 + 1].y); \
            u.z = pack2(rb[q2 * 2].z, rb[q2 * 2 + 1].z); \
            u.w = pack2(rb[q2 * 2].w, rb[q2 * 2 + 1].w); \
            *(uint4*)&Bs_[(bufi) * BSZ + kp * 136 + bq * 4] = u; \
        } \
    } while (0)
    #define DN_COMP(kf) do { \
        uint32_t a[4][4]; \
        _Pragma("unroll") \
        for (int mf = 0; mf < 4; mf++) \
            ldsm4(a[mf], Aaddr + mf * 1280 + (kf) * 32); \
        _Pragma("unroll") \
        for (int nf = 0; nf < 8; nf++) { \
            const int ob = bbase + (kf) * 1088 + nf * 8; \
            const uint32_t b0 = Bb[ob], b1 = Bb[ob + 544]; \
            _Pragma("unroll") \
            for (int mf = 0; mf < 4; mf++) \
                mma16(cc[mf][nf], a[mf], b0, b1); \
        } \
    } while (0)

    DN_LDGA(0, 0);  DN_LDGB(0, 0);  DN_STS(0, 0);
    DN_LDGA(0, 1);  DN_LDGB(0, 1);  DN_STS(0, 1);
    __syncthreads();

    const int NC = IDIM / 32;
    for (int c = 0; c < NC; c++) {
        const int buf = c & 1;
        const uint32_t Aaddr = As_bytes + (uint32_t)buf * (ASZ * 4) + a_off;
        const uint32_t* Bb = Bs_ + buf * BSZ;
        const bool more = (c + 1 < NC);
        if (more) { DN_LDGA((c + 1) * 32, 0); DN_LDGB((c + 1) * 32, 0); }
        DN_COMP(0);
        if (more) { DN_STS(buf ^ 1, 0); DN_LDGA((c + 1) * 32, 1); DN_LDGB((c + 1) * 32, 1); }
        DN_COMP(1);
        if (more) { DN_STS(buf ^ 1, 1); }
        __syncthreads();
    }
    #undef DN_LDGA
    #undef DN_LDGB
    #undef DN_STS
    #undef DN_COMP

    #pragma unroll
    for (int mf = 0; mf < 4; mf++) {
        #pragma unroll
        for (int nf = 0; nf < 8; nf++) {
            const int row0 = m0 + wm * 64 + mf * 16 + g;
            const int col  = n0 + wn * 64 + nf * 8 + tig * 2;
            if (row0 < n_e) {
                float* dst = EXP ? (g_dbuf + ((size_t)ez * CAP + row0) * HDIM + col)
                                 : (out + (size_t)row0 * HDIM + col);
                *(float2*)dst = make_float2(cc[mf][nf][0], cc[mf][nf][1]);
            }
            if (row0 + 8 < n_e) {
                float* dst = EXP ? (g_dbuf + ((size_t)ez * CAP + row0 + 8) * HDIM + col)
                                 : (out + (size_t)(row0 + 8) * HDIM + col);
                *(float2*)dst = make_float2(cc[mf][nf][2], cc[mf][nf][3]);
            }
        }
    }
}

// ---------------- combine ----------------
__global__ void __launch_bounds__(256)
combine_kernel(float* __restrict__ out) {
    const int t = blockIdx.x;
    const int i = threadIdx.x;
    float4 acc = ((const float4*)out)[(size_t)t * 256 + i];
    #pragma unroll
    for (int k = 0; k < KTOP; k++) {
        const int e = g_e4[t * KTOP + k];
        const int s = g_s4[t * KTOP + k];
        const float w = g_w4[t * KTOP + k];
        if (s < CAP) {
            const float4 v = ((const float4*)g_dbuf)[((size_t)e * CAP + s) * (HDIM / 4) + i];
            acc.x += w * v.x; acc.y += w * v.y; acc.z += w * v.z; acc.w += w * v.w;
        }
    }
    ((float4*)out)[(size_t)t * 256 + i] = acc;
}

extern "C" void kernel_launch(void* const* d_in, const int* in_sizes, int n_in,
                              void* d_out, int out_size) {
    const float* x   = (const float*)d_in[0];
    const float* gw  = (const float*)d_in[1];
    const float* wgu = (const float*)d_in[2];
    const float* wd  = (const float*)d_in[3];
    const float* sgu = (const float*)d_in[4];
    const float* sd  = (const float*)d_in[5];
    float* out = (float*)d_out;
    (void)in_sizes; (void)n_in; (void)out_size;

    zero_counts_kernel<<<1, 32>>>();
    router_kernel<<<TTOK, 128>>>(x, gw);

    // merged expert+shared gate-up: 2048 expert blocks + 256 shared blocks
    gu_mma<<<2304, 128>>>(x, wgu, sgu);
    // merged expert+shared down
    dn_mma<<<2304, 128>>>(wd, sd, out);

    combine_kernel<<<TTOK, 256>>>(out);
}

// round 13
// speedup vs baseline: 1.3606x; 1.1968x over previous
#include <cuda_runtime.h>
#include <cuda_fp16.h>
#include <math.h>
#include <stdint.h>

#define NE    32
#define KTOP  4
#define HDIM  1024
#define IDIM  512
#define TTOK  4096
#define CAP   1024

// ---------------- device scratch ----------------
__device__ int    g_count[NE];
__device__ int    g_tok[NE * CAP];
__device__ int    g_e4[TTOK * KTOP];
__device__ int    g_s4[TTOK * KTOP];
__device__ float  g_w4[TTOK * KTOP];
__device__ __half g_xh[(size_t)TTOK * HDIM];          // fp16 copy of x
__device__ __half g_act[(size_t)NE * CAP * IDIM];     // fp16 silu(g)*u
__device__ __half g_shact[(size_t)TTOK * IDIM];       // fp16 shared act
__device__ __half g_dbuf[(size_t)NE * CAP * HDIM];    // fp16 per-slot down out

// ---------------- helpers ----------------
__device__ __forceinline__ uint32_t pack2(float lo, float hi) {
    __half2 h = __floats2half2_rn(lo, hi);
    return *(uint32_t*)&h;
}
__device__ __forceinline__ void mma16(float* c, const uint32_t* a,
                                      uint32_t b0, uint32_t b1) {
    asm volatile(
        "mma.sync.aligned.m16n8k16.row.col.f32.f16.f16.f32 "
        "{%0,%1,%2,%3}, {%4,%5,%6,%7}, {%8,%9}, {%0,%1,%2,%3};"
        : "+f"(c[0]), "+f"(c[1]), "+f"(c[2]), "+f"(c[3])
        : "r"(a[0]), "r"(a[1]), "r"(a[2]), "r"(a[3]), "r"(b0), "r"(b1));
}
__device__ __forceinline__ void ldsm4(uint32_t* r, uint32_t saddr) {
    asm volatile("ldmatrix.sync.aligned.m8n8.x4.shared.b16 {%0,%1,%2,%3}, [%4];"
        : "=r"(r[0]), "=r"(r[1]), "=r"(r[2]), "=r"(r[3]) : "r"(saddr));
}
__device__ __forceinline__ uint32_t smem_u32(const void* p) {
    return (uint32_t)__cvta_generic_to_shared(p);
}

// ---------------- x -> fp16 convert ----------------
__global__ void __launch_bounds__(256)
cvt_x_kernel(const float* __restrict__ x) {
    const int i = blockIdx.x * 256 + threadIdx.x;       // 4 floats each
    const float4 v = ((const float4*)x)[i];
    __half2 h0 = __floats2half2_rn(v.x, v.y);
    __half2 h1 = __floats2half2_rn(v.z, v.w);
    ((uint2*)g_xh)[i] = make_uint2(*(uint32_t*)&h0, *(uint32_t*)&h1);
}

// ---------------- router ----------------
__global__ void zero_counts_kernel() {
    if (threadIdx.x < NE) g_count[threadIdx.x] = 0;
}

__global__ void router_kernel(const float* __restrict__ x,
                              const float* __restrict__ gw) {
    const int t = blockIdx.x;
    __shared__ float xs[HDIM];
    __shared__ float logits[NE];
    const float* xr = x + (size_t)t * HDIM;
    for (int i = threadIdx.x; i < HDIM; i += 128) xs[i] = xr[i];
    __syncthreads();

    const int warp = threadIdx.x >> 5, lane = threadIdx.x & 31;
    for (int i = 0; i < 8; i++) {
        const int e = warp * 8 + i;
        const float* w = gw + (size_t)e * HDIM;
        float s = 0.f;
        #pragma unroll 8
        for (int j = lane; j < HDIM; j += 32) s += xs[j] * w[j];
        #pragma unroll
        for (int o = 16; o > 0; o >>= 1) s += __shfl_down_sync(0xffffffffu, s, o);
        if (lane == 0) logits[e] = s;
    }
    __syncthreads();

    if (threadIdx.x == 0) {
        float mx = logits[0];
        #pragma unroll
        for (int e = 1; e < NE; e++) mx = fmaxf(mx, logits[e]);
        float p[NE];
        #pragma unroll
        for (int e = 0; e < NE; e++) p[e] = expf(logits[e] - mx);
        int idx[KTOP]; float pv[KTOP]; float psum = 0.f;
        bool used[NE];
        #pragma unroll
        for (int e = 0; e < NE; e++) used[e] = false;
        for (int k = 0; k < KTOP; k++) {
            float best = -1.f; int bi = 0;
            for (int e = 0; e < NE; e++)
                if (!used[e] && p[e] > best) { best = p[e]; bi = e; }
            used[bi] = true; idx[k] = bi; pv[k] = best; psum += best;
        }
        const float inv = 1.f / psum;
        for (int k = 0; k < KTOP; k++) {
            const int e = idx[k];
            const int pos = atomicAdd(&g_count[e], 1);
            if (pos < CAP) g_tok[e * CAP + pos] = t;
            g_e4[t * KTOP + k] = e;
            g_s4[t * KTOP + k] = pos;
            g_w4[t * KTOP + k] = pv[k] * inv;
        }
    }
}

// ---------------- GEMM layout (fp16 half2 along K) ----------------
// A smem: 128 rows x 16 kp words, row stride 20 (LDSM conflict-free).
// B smem: 16 kp x 128 n, row stride 136 (scalar frag LDS conflict-free).
#define ASZ 2560   // words
#define BSZ 2176   // words

// Merged grid decode: bids [0,2048) expert (ez=bid>>6, my=(bid>>3)&7, nx=bid&7);
// bids [2048,2304) shared (my=r>>3, nx=r&7).

// ---------------- gate-up (fp16 mma.sync, fused silu, merged) ----------------
// 128 thr, 4 warps (2M x 2N). block M=128, N=64 gate + 64 up. warp m64.
__global__ void __launch_bounds__(128)
gu_mma(const float* __restrict__ Wge, const float* __restrict__ Wgs) {
    const int bid = blockIdx.x;
    const bool EXP = bid < 2048;
    int ez, my, nx;
    if (EXP) { ez = bid >> 6; my = (bid >> 3) & 7; nx = bid & 7; }
    else     { const int r = bid - 2048; ez = 0; my = r >> 3; nx = r & 7; }
    const int n_e = EXP ? min(g_count[ez], CAP) : TTOK;
    const int m0 = my * 128;
    if (m0 >= n_e) return;
    const int n0 = nx * 64;

    __shared__ uint32_t As_[2 * ASZ];
    __shared__ uint32_t Bs_[2 * BSZ];

    const int tid = threadIdx.x;
    const int wid = tid >> 5, lane = tid & 31;
    const int g = lane >> 2, tig = lane & 3;
    const int wm = wid & 1, wn = wid >> 1;

    const float* W = EXP ? Wge + (size_t)ez * HDIM * (2 * IDIM) : Wgs;
    __half* actb = EXP ? g_act + (size_t)ez * CAP * IDIM : g_shact;

    // A staging: one fp16 row per thread
    const __half* arow = nullptr;
    {
        const int r = m0 + tid;
        if (r < n_e) arow = g_xh + (size_t)(EXP ? g_tok[ez * CAP + r] : r) * HDIM;
    }
    const int bk = wid, bq = lane;
    const int bcol = (bq < 16) ? (n0 + bq * 4) : (IDIM + n0 + (bq - 16) * 4);

    float cg[4][4][4], cu[4][4][4];
    #pragma unroll
    for (int a = 0; a < 4; a++)
        #pragma unroll
        for (int b = 0; b < 4; b++)
            #pragma unroll
            for (int d = 0; d < 4; d++) { cg[a][b][d] = 0.f; cu[a][b][d] = 0.f; }

    const uint32_t As_bytes = smem_u32(As_);
    const int lrow = (lane & 7) + ((lane >> 3) & 1) * 8;
    const int lcol = (lane >> 4) * 4;
    const uint32_t a_off = (uint32_t)(((wm * 64 + lrow) * 20 + lcol) * 4);
    const int bbase = tig * 136 + wn * 32 + g;

    uint4 ra16[2];
    float4 rb[4];
    #define GU_LDGA(k0, h) do { \
        if (arow) { \
            ra16[0] = *(const uint4*)(arow + (k0) + (h) * 16); \
            ra16[1] = *(const uint4*)(arow + (k0) + (h) * 16 + 8); \
        } else { \
            ra16[0] = make_uint4(0u, 0u, 0u, 0u); \
            ra16[1] = make_uint4(0u, 0u, 0u, 0u); \
        } \
    } while (0)
    #define GU_LDGB(k0, h) do { \
        _Pragma("unroll") \
        for (int q2 = 0; q2 < 2; q2++) { \
            const int kk = (k0) + 2 * (bk + ((h) * 2 + q2) * 4); \
            rb[q2 * 2 + 0] = *(const float4*)(W + (size_t)kk * (2 * IDIM) + bcol); \
            rb[q2 * 2 + 1] = *(const float4*)(W + (size_t)(kk + 1) * (2 * IDIM) + bcol); \
        } \
    } while (0)
    #define GU_STS(bufi, h) do { \
        *(uint4*)&As_[(bufi) * ASZ + tid * 20 + (h) * 8 + 0] = ra16[0]; \
        *(uint4*)&As_[(bufi) * ASZ + tid * 20 + (h) * 8 + 4] = ra16[1]; \
        _Pragma("unroll") \
        for (int q2 = 0; q2 < 2; q2++) { \
            const int kp = bk + ((h) * 2 + q2) * 4; \
            uint4 u; \
            u.x = pack2(rb[q2 * 2].x, rb[q2 * 2 + 1].x); \
            u.y = pack2(rb[q2 * 2].y, rb[q2 * 2 + 1].y); \
            u.z = pack2(rb[q2 * 2].z, rb[q2 * 2 + 1].z); \
            u.w = pack2(rb[q2 * 2].w, rb[q2 * 2 + 1].w); \
            *(uint4*)&Bs_[(bufi) * BSZ + kp * 136 + bq * 4] = u; \
        } \
    } while (0)
    #define GU_COMP(kf) do { \
        uint32_t a[4][4]; \
        _Pragma("unroll") \
        for (int mf = 0; mf < 4; mf++) \
            ldsm4(a[mf], Aaddr + mf * 1280 + (kf) * 32); \
        _Pragma("unroll") \
        for (int nf = 0; nf < 4; nf++) { \
            const int ob = bbase + (kf) * 1088 + nf * 8; \
            const uint32_t bg0 = Bb[ob],      bg1 = Bb[ob + 544]; \
            const uint32_t bu0 = Bb[ob + 64], bu1 = Bb[ob + 608]; \
            _Pragma("unroll") \
            for (int mf = 0; mf < 4; mf++) { \
                mma16(cg[mf][nf], a[mf], bg0, bg1); \
                mma16(cu[mf][nf], a[mf], bu0, bu1); \
            } \
        } \
    } while (0)

    GU_LDGA(0, 0);  GU_LDGB(0, 0);  GU_STS(0, 0);
    GU_LDGA(0, 1);  GU_LDGB(0, 1);  GU_STS(0, 1);
    __syncthreads();

    const int NC = HDIM / 32;
    for (int c = 0; c < NC; c++) {
        const int buf = c & 1;
        const uint32_t Aaddr = As_bytes + (uint32_t)buf * (ASZ * 4) + a_off;
        const uint32_t* Bb = Bs_ + buf * BSZ;
        const bool more = (c + 1 < NC);
        if (more) { GU_LDGA((c + 1) * 32, 0); GU_LDGB((c + 1) * 32, 0); }
        GU_COMP(0);
        if (more) { GU_STS(buf ^ 1, 0); GU_LDGA((c + 1) * 32, 1); GU_LDGB((c + 1) * 32, 1); }
        GU_COMP(1);
        if (more) { GU_STS(buf ^ 1, 1); }
        __syncthreads();
    }
    #undef GU_LDGA
    #undef GU_LDGB
    #undef GU_STS
    #undef GU_COMP

    // epilogue: silu(gate)*up -> fp16 act
    #pragma unroll
    for (int mf = 0; mf < 4; mf++) {
        #pragma unroll
        for (int nf = 0; nf < 4; nf++) {
            const int row0 = m0 + wm * 64 + mf * 16 + g;
            const int col  = n0 + wn * 32 + nf * 8 + tig * 2;
            if (row0 < n_e) {
                float gv, uv, ox, oy;
                gv = cg[mf][nf][0]; uv = cu[mf][nf][0]; ox = gv / (1.f + __expf(-gv)) * uv;
                gv = cg[mf][nf][1]; uv = cu[mf][nf][1]; oy = gv / (1.f + __expf(-gv)) * uv;
                *(__half2*)(actb + (size_t)row0 * IDIM + col) = __floats2half2_rn(ox, oy);
            }
            if (row0 + 8 < n_e) {
                float gv, uv, ox, oy;
                gv = cg[mf][nf][2]; uv = cu[mf][nf][2]; ox = gv / (1.f + __expf(-gv)) * uv;
                gv = cg[mf][nf][3]; uv = cu[mf][nf][3]; oy = gv / (1.f + __expf(-gv)) * uv;
                *(__half2*)(actb + (size_t)(row0 + 8) * IDIM + col) = __floats2half2_rn(ox, oy);
            }
        }
    }
}

// ---------------- down (fp16 mma.sync, merged) ----------------
// 128 thr, 4 warps (2M x 2N). block M=128 x N=128; warp m64 x n64.
__global__ void __launch_bounds__(128)
dn_mma(const float* __restrict__ Wde, const float* __restrict__ Wds,
       float* __restrict__ out) {
    const int bid = blockIdx.x;
    const bool EXP = bid < 2048;
    int ez, my, nx;
    if (EXP) { ez = bid >> 6; my = (bid >> 3) & 7; nx = bid & 7; }
    else     { const int r = bid - 2048; ez = 0; my = r >> 3; nx = r & 7; }
    const int n_e = EXP ? min(g_count[ez], CAP) : TTOK;
    const int m0 = my * 128;
    if (m0 >= n_e) return;
    const int n0 = nx * 128;

    __shared__ uint32_t As_[2 * ASZ];
    __shared__ uint32_t Bs_[2 * BSZ];

    const int tid = threadIdx.x;
    const int wid = tid >> 5, lane = tid & 31;
    const int g = lane >> 2, tig = lane & 3;
    const int wm = wid & 1, wn = wid >> 1;

    const __half* actb = EXP ? g_act + (size_t)ez * CAP * IDIM : g_shact;
    const float* W = EXP ? Wde + (size_t)ez * IDIM * HDIM : Wds;

    const __half* arow = actb + (size_t)(m0 + tid) * IDIM;
    const int bk = wid, bq = lane;
    const int bcol = n0 + bq * 4;

    float cc[4][8][4];
    #pragma unroll
    for (int a = 0; a < 4; a++)
        #pragma unroll
        for (int b = 0; b < 8; b++)
            #pragma unroll
            for (int d = 0; d < 4; d++) cc[a][b][d] = 0.f;

    const uint32_t As_bytes = smem_u32(As_);
    const int lrow = (lane & 7) + ((lane >> 3) & 1) * 8;
    const int lcol = (lane >> 4) * 4;
    const uint32_t a_off = (uint32_t)(((wm * 64 + lrow) * 20 + lcol) * 4);
    const int bbase = tig * 136 + wn * 64 + g;

    uint4 ra16[2];
    float4 rb[4];
    #define DN_LDGA(k0, h) do { \
        ra16[0] = *(const uint4*)(arow + (k0) + (h) * 16); \
        ra16[1] = *(const uint4*)(arow + (k0) + (h) * 16 + 8); \
    } while (0)
    #define DN_LDGB(k0, h) do { \
        _Pragma("unroll") \
        for (int q2 = 0; q2 < 2; q2++) { \
            const int kk = (k0) + 2 * (bk + ((h) * 2 + q2) * 4); \
            rb[q2 * 2 + 0] = *(const float4*)(W + (size_t)kk * HDIM + bcol); \
            rb[q2 * 2 + 1] = *(const float4*)(W + (size_t)(kk + 1) * HDIM + bcol); \
        } \
    } while (0)
    #define DN_STS(bufi, h) do { \
        *(uint4*)&As_[(bufi) * ASZ + tid * 20 + (h) * 8 + 0] = ra16[0]; \
        *(uint4*)&As_[(bufi) * ASZ + tid * 20 + (h) * 8 + 4] = ra16[1]; \
        _Pragma("unroll") \
        for (int q2 = 0; q2 < 2; q2++) { \
            const int kp = bk + ((h) * 2 + q2) * 4; \
            uint4 u; \
            u.x = pack2(rb[q2 * 2].x, rb[q2 * 2 + 1].x); \
            u.y = pack2(rb[q2 * 2].y, rb[q2 * 2 + 1].y); \
            u.z = pack2(rb[q2 * 2].z, rb[q2 * 2 + 1].z); \
            u.w = pack2(rb[q2 * 2].w, rb[q2 * 2 + 1].w); \
            *(uint4*)&Bs_[(bufi) * BSZ + kp * 136 + bq * 4] = u; \
        } \
    } while (0)
    #define DN_COMP(kf) do { \
        uint32_t a[4][4]; \
        _Pragma("unroll") \
        for (int mf = 0; mf < 4; mf++) \
            ldsm4(a[mf], Aaddr + mf * 1280 + (kf) * 32); \
        _Pragma("unroll") \
        for (int nf = 0; nf < 8; nf++) { \
            const int ob = bbase + (kf) * 1088 + nf * 8; \
            const uint32_t b0 = Bb[ob], b1 = Bb[ob + 544]; \
            _Pragma("unroll") \
            for (int mf = 0; mf < 4; mf++) \
                mma16(cc[mf][nf], a[mf], b0, b1); \
        } \
    } while (0)

    DN_LDGA(0, 0);  DN_LDGB(0, 0);  DN_STS(0, 0);
    DN_LDGA(0, 1);  DN_LDGB(0, 1);  DN_STS(0, 1);
    __syncthreads();

    const int NC = IDIM / 32;
    for (int c = 0; c < NC; c++) {
        const int buf = c & 1;
        const uint32_t Aaddr = As_bytes + (uint32_t)buf * (ASZ * 4) + a_off;
        const uint32_t* Bb = Bs_ + buf * BSZ;
        const bool more = (c + 1 < NC);
        if (more) { DN_LDGA((c + 1) * 32, 0); DN_LDGB((c + 1) * 32, 0); }
        DN_COMP(0);
        if (more) { DN_STS(buf ^ 1, 0); DN_LDGA((c + 1) * 32, 1); DN_LDGB((c + 1) * 32, 1); }
        DN_COMP(1);
        if (more) { DN_STS(buf ^ 1, 1); }
        __syncthreads();
    }
    #undef DN_LDGA
    #undef DN_LDGB
    #undef DN_STS
    #undef DN_COMP

    #pragma unroll
    for (int mf = 0; mf < 4; mf++) {
        #pragma unroll
        for (int nf = 0; nf < 8; nf++) {
            const int row0 = m0 + wm * 64 + mf * 16 + g;
            const int col  = n0 + wn * 64 + nf * 8 + tig * 2;
            if (row0 < n_e) {
                if (EXP) {
                    *(__half2*)(g_dbuf + ((size_t)ez * CAP + row0) * HDIM + col) =
                        __floats2half2_rn(cc[mf][nf][0], cc[mf][nf][1]);
                } else {
                    *(float2*)(out + (size_t)row0 * HDIM + col) =
                        make_float2(cc[mf][nf][0], cc[mf][nf][1]);
                }
            }
            if (row0 + 8 < n_e) {
                if (EXP) {
                    *(__half2*)(g_dbuf + ((size_t)ez * CAP + row0 + 8) * HDIM + col) =
                        __floats2half2_rn(cc[mf][nf][2], cc[mf][nf][3]);
                } else {
                    *(float2*)(out + (size_t)(row0 + 8) * HDIM + col) =
                        make_float2(cc[mf][nf][2], cc[mf][nf][3]);
                }
            }
        }
    }
}

// ---------------- combine: out[t] += sum_k w_k * fp16 dbuf[e_k, s_k] --------
__global__ void __launch_bounds__(128)
combine_kernel(float* __restrict__ out) {
    const int t = blockIdx.x;
    const int i = threadIdx.x;                       // 8 floats per thread
    float4* outv = (float4*)out + (size_t)t * 256 + i * 2;
    float4 a0 = outv[0], a1 = outv[1];
    #pragma unroll
    for (int k = 0; k < KTOP; k++) {
        const int e = g_e4[t * KTOP + k];
        const int s = g_s4[t * KTOP + k];
        const float w = g_w4[t * KTOP + k];
        if (s < CAP) {
            const uint4 hv = *(const uint4*)(g_dbuf + ((size_t)e * CAP + s) * HDIM + i * 8);
            const float2 f0 = __half22float2(*(const __half2*)&hv.x);
            const float2 f1 = __half22float2(*(const __half2*)&hv.y);
            const float2 f2 = __half22float2(*(const __half2*)&hv.z);
            const float2 f3 = __half22float2(*(const __half2*)&hv.w);
            a0.x += w * f0.x; a0.y += w * f0.y; a0.z += w * f1.x; a0.w += w * f1.y;
            a1.x += w * f2.x; a1.y += w * f2.y; a1.z += w * f3.x; a1.w += w * f3.y;
        }
    }
    outv[0] = a0; outv[1] = a1;
}

extern "C" void kernel_launch(void* const* d_in, const int* in_sizes, int n_in,
                              void* d_out, int out_size) {
    const float* x   = (const float*)d_in[0];
    const float* gw  = (const float*)d_in[1];
    const float* wgu = (const float*)d_in[2];
    const float* wd  = (const float*)d_in[3];
    const float* sgu = (const float*)d_in[4];
    const float* sd  = (const float*)d_in[5];
    float* out = (float*)d_out;
    (void)in_sizes; (void)n_in; (void)out_size;

    zero_counts_kernel<<<1, 32>>>();
    cvt_x_kernel<<<(TTOK * HDIM) / 1024, 256>>>(x);
    router_kernel<<<TTOK, 128>>>(x, gw);

    gu_mma<<<2304, 128>>>(wgu, sgu);
    dn_mma<<<2304, 128>>>(wd, sd, out);

    combine_kernel<<<TTOK, 128>>>(out);
}